// round 15
// baseline (speedup 1.0000x reference)
#include <cuda_runtime.h>

#define BB 32
#define NN 4096
#define DD 256
#define HH 8
#define TT 28
#define ROWS (BB * NN)
#define BLKA 128
#define RPBA 32             // rows per tile, kernel A
#define NTILES (ROWS / RPBA)
#define GRIDA (148 * 3)     // persistent: 3 CTAs per SM
#define BLKB 64
#define RPBB 64             // rows per block, kernel B (4 threads/row, 4 rows/thread)

typedef unsigned long long u64;

// 8 MB scratch: per row 16 floats = [h0 lanes 0..7 | g1pre lanes 0..7]
__device__ __align__(16) float g_proj[ROWS * 16];

// ---------- packed f32x2 ops on opaque u64 register pairs ----------
__device__ __forceinline__ u64 ffma2(u64 a, u64 b, u64 c) {
    u64 d; asm("fma.rn.f32x2 %0, %1, %2, %3;" : "=l"(d) : "l"(a), "l"(b), "l"(c)); return d;
}
__device__ __forceinline__ u64 fadd2(u64 a, u64 b) {
    u64 d; asm("add.rn.f32x2 %0, %1, %2;" : "=l"(d) : "l"(a), "l"(b)); return d;
}
__device__ __forceinline__ u64 pk(float lo, float hi) {
    u64 r; asm("mov.b64 %0, {%1,%2};" : "=l"(r) : "f"(lo), "f"(hi)); return r;
}
__device__ __forceinline__ float2 upk(u64 v) {
    float2 f; asm("mov.b64 {%0,%1}, %2;" : "=f"(f.x), "=f"(f.y) : "l"(v)); return f;
}
__device__ __forceinline__ u64 dup2(float v) { return pk(v, v); }

__device__ __forceinline__ float tanhapx(float x) {
    float y; asm("tanh.approx.f32 %0, %1;" : "=f"(y) : "f"(x)); return y;
}

__device__ __forceinline__ void cp16(void* smem_dst, const void* gsrc) {
    unsigned sa = (unsigned)__cvta_generic_to_shared(smem_dst);
    asm volatile("cp.async.cg.shared.global [%0], [%1], 16;" :: "r"(sa), "l"(gsrc) : "memory");
}
__device__ __forceinline__ void cp_commit() {
    asm volatile("cp.async.commit_group;" ::: "memory");
}
__device__ __forceinline__ void cp_wait0() {
    asm volatile("cp.async.wait_group 0;" ::: "memory");
}

#define NEG1U 0xBF800000BF800000ULL  // (-1.0f, -1.0f)

// input pre-scaled by 0.5: sigmoid(2v) = 0.5*tanh(v) + 0.5
__device__ __forceinline__ u64 sigmoid2h(u64 v) {
    float2 f = upk(v);
    return pk(fmaf(0.5f, tanhapx(f.x), 0.5f), fmaf(0.5f, tanhapx(f.y), 0.5f));
}
__device__ __forceinline__ u64 tanh2t(u64 v) {
    float2 f = upk(v);
    return pk(tanhapx(f.x), tanhapx(f.y));
}

// ============ Kernel A: persistent projection GEMM with cp.async pipeline ============
struct SmemA {
    float4     xs[2][RPBA][32];   // double-buffered stage (32KB)
    ulonglong2 wq[64 * 17];       // [chunk][e*4 + pg*2 + i] + pad (17KB)
};

__global__ void __launch_bounds__(BLKA)
proj_kernel(const float* __restrict__ x,
            const float* __restrict__ Wp, const float* __restrict__ Wg1) {
    __shared__ SmemA s;
    const int tid = threadIdx.x;
    const unsigned FULL = 0xFFFFFFFFu;

    const int pg  = tid >> 6;
    const int rgp = (tid >> 4) & 3;
    const int ds  = tid & 15;

    for (int idx = tid; idx < 64 * 16; idx += BLKA) {
        int chunk = idx >> 4, r = idx & 15;
        int e = r >> 2, pgw = (r >> 1) & 1, i = r & 1;
        int d = chunk * 4 + e;
        const float* W = pgw ? Wg1 : Wp;
        s.wq[chunk * 17 + e * 4 + pgw * 2 + i] = make_ulonglong2(
            pk(W[(4 * i + 0) * DD + d], W[(4 * i + 1) * DD + d]),
            pk(W[(4 * i + 2) * DD + d], W[(4 * i + 3) * DD + d]));
    }

    auto issue_unit = [&](int tile, int cst, int buf) {
#pragma unroll
        for (int k = 0; k < 8; k++) {
            int f = k * BLKA + tid;
            int row = f >> 5, q = f & 31;
            cp16(&s.xs[buf][row][q],
                 x + (size_t)(tile * RPBA + row) * DD + cst * 128 + q * 4);
        }
        cp_commit();
    };

    const int stride = gridDim.x;
    const int t0 = blockIdx.x;
    if (t0 >= NTILES) return;

    u64 acc[32];
    issue_unit(t0, 0, 0);

    int k = 0;
    for (int tile = t0; tile < NTILES; tile += stride) {
#pragma unroll 1
        for (int cst = 0; cst < 2; cst++, k++) {
            int buf = k & 1;
            cp_wait0();
            __syncthreads();
            {
                int nk = k + 1;
                int ncst = nk & 1;
                int ntile = tile + (ncst == 0 ? stride : 0);
                if (ntile < NTILES) issue_unit(ntile, ncst, buf ^ 1);
            }
            if (cst == 0) {
#pragma unroll
                for (int i = 0; i < 32; i++) acc[i] = 0ULL;
            }
#pragma unroll 1
            for (int m2 = 0; m2 < 2; m2++) {
                int chunkL = ds + 16 * m2;
                int chunkG = cst * 32 + chunkL;
                ulonglong2 w[8];
#pragma unroll
                for (int e = 0; e < 4; e++) {
                    w[2 * e]     = s.wq[chunkG * 17 + e * 4 + pg * 2 + 0];
                    w[2 * e + 1] = s.wq[chunkG * 17 + e * 4 + pg * 2 + 1];
                }
#pragma unroll
                for (int r = 0; r < 8; r++) {
                    float4 xv = s.xs[buf][rgp * 8 + r][chunkL];
#pragma unroll
                    for (int e = 0; e < 4; e++) {
                        float xe = (e == 0) ? xv.x : (e == 1) ? xv.y : (e == 2) ? xv.z : xv.w;
                        u64 xd = dup2(xe);
                        acc[r * 4 + 0] = ffma2(w[2 * e].x,     xd, acc[r * 4 + 0]);
                        acc[r * 4 + 1] = ffma2(w[2 * e].y,     xd, acc[r * 4 + 1]);
                        acc[r * 4 + 2] = ffma2(w[2 * e + 1].x, xd, acc[r * 4 + 2]);
                        acc[r * 4 + 3] = ffma2(w[2 * e + 1].y, xd, acc[r * 4 + 3]);
                    }
                }
            }
            if (cst == 1) {
#define REDROUND(cnt, bit) { int db = ds & (bit); \
    _Pragma("unroll") \
    for (int i = 0; i < (cnt) / 2; i++) { \
        u64 snd = db ? acc[i] : acc[i + (cnt) / 2]; \
        u64 rcv = __shfl_xor_sync(FULL, snd, (bit)); \
        u64 kp  = db ? acc[i + (cnt) / 2] : acc[i]; \
        acc[i] = fadd2(kp, rcv); \
    } }
                REDROUND(32, 1)
                REDROUND(16, 2)
                REDROUND(8, 4)
                REDROUND(4, 8)
#undef REDROUND
                int r_own = 4 * (ds & 1) + 2 * ((ds >> 1) & 1) + ((ds >> 2) & 1);
                int b = (ds >> 3) & 1;
                int row = tile * RPBA + rgp * 8 + r_own;
                *(ulonglong2*)&g_proj[row * 16 + pg * 8 + 4 * b] =
                    make_ulonglong2(acc[0], acc[1]);
            }
        }
    }
}

// ====== Kernel B: GRU rollout (4 threads/row, 4 rows/thread, weights in regs) =======
#define NR 4                 // rows per thread
struct SmemB {
    u64 gf[RPBB][TT];        // (gate, (1-gate)*decay) per row per t (14KB)
};

__global__ void __launch_bounds__(BLKB)
gru_kernel(const float* __restrict__ last_step,
           const float* __restrict__ W_ih, const float* __restrict__ W_hh,
           const float* __restrict__ b_ih, const float* __restrict__ b_hh,
           const float* __restrict__ bp, const float* __restrict__ Wo,
           const float* __restrict__ bo, const float* __restrict__ bg1,
           const float* __restrict__ Wg2, const float* __restrict__ bg2,
           const float* __restrict__ log_decay, float* __restrict__ out) {
    __shared__ SmemB s;
    const int tid = threadIdx.x;
    const int sub = tid & 3;
    const int rl  = tid >> 2;           // row slot 0..15; rows = rl + 16*r
    const int rb  = blockIdx.x * RPBB;
    const int L0  = 2 * sub, L1 = L0 + 1;
    const unsigned FULL = 0xFFFFFFFFu;

    const u64 bpq  = pk(bp[L0], bp[L1]);
    const u64 bg1q = pk(bg1[L0], bg1[L1]);

    u64 hq[NR], g1q[NR];
    float lastv[NR];
#pragma unroll
    for (int r = 0; r < NR; r++) {
        int row = rb + rl + 16 * r;
        float2 hv = *(const float2*)&g_proj[row * 16 + 2 * sub];
        float2 gv = *(const float2*)&g_proj[row * 16 + 8 + 2 * sub];
        hq[r] = fadd2(pk(hv.x, hv.y), bpq);
        float2 f = upk(fadd2(pk(gv.x, gv.y), bg1q));
        g1q[r] = pk(fmaxf(f.x, 0.0f), fmaxf(f.y, 0.0f));
        lastv[r] = last_step[row];
    }

    // precompute (gate, (1-gate)*decay) per t for all rows
    {
        float edc = __expf(log_decay[0]);
        int j0 = 2 * (sub ^ 0), j1 = 2 * (sub ^ 1), j2 = 2 * (sub ^ 2), j3 = 2 * (sub ^ 3);
#pragma unroll
        for (int r = 0; r < NR; r++) {
            u64 gq = g1q[r];
            u64 gA = __shfl_xor_sync(FULL, gq, 1);
            u64 gB = __shfl_xor_sync(FULL, gq, 2);
            u64 gC = __shfl_xor_sync(FULL, gq, 3);
            float2 g0 = upk(gq), g1v = upk(gA), g2v = upk(gB), g3v = upk(gC);
#pragma unroll
            for (int kk = 0; kk < 7; kk++) {
                int t = 4 * kk + sub;
                const float* wr = Wg2 + t * HH;
                float lg = bg2[t];
                lg = fmaf(g0.x, wr[j0], lg);     lg = fmaf(g0.y, wr[j0 + 1], lg);
                lg = fmaf(g1v.x, wr[j1], lg);    lg = fmaf(g1v.y, wr[j1 + 1], lg);
                lg = fmaf(g2v.x, wr[j2], lg);    lg = fmaf(g2v.y, wr[j2 + 1], lg);
                lg = fmaf(g3v.x, wr[j3], lg);    lg = fmaf(g3v.y, wr[j3 + 1], lg);
                float gate = fmaf(0.5f, tanhapx(0.5f * lg), 0.5f);
                float gd = lastv[r] * __expf(-edc * (float)(t + 1));
                s.gf[rl + 16 * r][t] = pk(gate, (1.0f - gate) * gd);
            }
        }
    }

    // hoist GRU weights (slot-permuted to match shuffles); r/z pre-scaled by 0.5
    u64 whr[8], whz[8], whn[8], wo4[4];
#pragma unroll
    for (int p = 0; p < 4; p++) {
        int j0 = 2 * (sub ^ p);
#pragma unroll
        for (int b = 0; b < 2; b++) {
            int j = j0 + b, idx = 2 * p + b;
            whr[idx] = pk(0.5f * W_hh[L0 * HH + j],        0.5f * W_hh[L1 * HH + j]);
            whz[idx] = pk(0.5f * W_hh[(8 + L0) * HH + j],  0.5f * W_hh[(8 + L1) * HH + j]);
            whn[idx] = pk(W_hh[(16 + L0) * HH + j],        W_hh[(16 + L1) * HH + j]);
        }
        wo4[p] = pk(Wo[j0], Wo[j0 + 1]);
    }
    u64 wihr = pk(0.5f * W_ih[L0], 0.5f * W_ih[L1]);
    u64 wihz = pk(0.5f * W_ih[8 + L0], 0.5f * W_ih[8 + L1]);
    u64 wihn = pk(W_ih[16 + L0], W_ih[16 + L1]);
    u64 bsr  = pk(0.5f * (b_ih[L0] + b_hh[L0]), 0.5f * (b_ih[L1] + b_hh[L1]));
    u64 bsz  = pk(0.5f * (b_ih[8 + L0] + b_hh[8 + L0]), 0.5f * (b_ih[8 + L1] + b_hh[8 + L1]));
    u64 bain = pk(b_ih[16 + L0], b_ih[16 + L1]);
    u64 bahn = pk(b_hh[16 + L0], b_hh[16 + L1]);
    const float bo_r = bo[0];

    float cur[NR];
#pragma unroll
    for (int r = 0; r < NR; r++) cur[r] = lastv[r];

#pragma unroll 1
    for (int t = 0; t <= TT; t++) {
        u64 e1[NR], e2[NR], e3[NR];
#pragma unroll
        for (int r = 0; r < NR; r++) e1[r] = __shfl_xor_sync(FULL, hq[r], 1);
#pragma unroll
        for (int r = 0; r < NR; r++) e2[r] = __shfl_xor_sync(FULL, hq[r], 2);
#pragma unroll
        for (int r = 0; r < NR; r++) e3[r] = __shfl_xor_sync(FULL, hq[r], 3);

        float p[NR];
#pragma unroll
        for (int r = 0; r < NR; r++) {
            u64 pp = ffma2(hq[r], wo4[0], 0ULL);
            pp = ffma2(e1[r], wo4[1], pp);
            pp = ffma2(e2[r], wo4[2], pp);
            pp = ffma2(e3[r], wo4[3], pp);
            float2 pf = upk(pp);
            p[r] = pf.x + pf.y + bo_r;
        }
        if (t > 0) {
#pragma unroll
            for (int r = 0; r < NR; r++) {
                cur[r] = p[r];
                if (((t - 1) & 3) == sub) {
                    float2 gg = upk(s.gf[rl + 16 * r][t - 1]);
                    out[(size_t)(rb + rl + 16 * r) * TT + (t - 1)] = fmaf(gg.x, p[r], gg.y);
                }
            }
        }
        if (t == TT) break;

        u64 ar[NR], az[NR], ai[NR], ah[NR];
#pragma unroll
        for (int r = 0; r < NR; r++) {
            u64 curd = dup2(cur[r]);
            ar[r] = ffma2(wihr, curd, bsr);
            az[r] = ffma2(wihz, curd, bsz);
            ai[r] = ffma2(wihn, curd, bain);
            ah[r] = bahn;
        }
#pragma unroll
        for (int jj = 0; jj < 8; jj++) {
            int half = jj & 1;
#pragma unroll
            for (int r = 0; r < NR; r++) {
                u64 src = (jj < 2) ? hq[r] : (jj < 4) ? e1[r] : (jj < 6) ? e2[r] : e3[r];
                float2 sf = upk(src);
                u64 hd = dup2(half ? sf.y : sf.x);
                ar[r] = ffma2(whr[jj], hd, ar[r]);
                az[r] = ffma2(whz[jj], hd, az[r]);
                ah[r] = ffma2(whn[jj], hd, ah[r]);
            }
        }
#pragma unroll
        for (int r = 0; r < NR; r++) {
            u64 rr = sigmoid2h(ar[r]);
            u64 zz = sigmoid2h(az[r]);
            u64 nn = tanh2t(ffma2(rr, ah[r], ai[r]));
            u64 dd = ffma2(nn, NEG1U, hq[r]);
            hq[r] = ffma2(zz, dd, nn);
        }
    }
}

extern "C" void kernel_launch(void* const* d_in, const int* in_sizes, int n_in,
                              void* d_out, int out_size) {
    const float* x         = (const float*)d_in[0];
    const float* last_step = (const float*)d_in[1];
    const float* W_ih      = (const float*)d_in[2];
    const float* W_hh      = (const float*)d_in[3];
    const float* b_ih      = (const float*)d_in[4];
    const float* b_hh      = (const float*)d_in[5];
    const float* Wp        = (const float*)d_in[6];
    const float* bp        = (const float*)d_in[7];
    const float* Wo        = (const float*)d_in[8];
    const float* bo        = (const float*)d_in[9];
    const float* Wg1       = (const float*)d_in[10];
    const float* bg1       = (const float*)d_in[11];
    const float* Wg2       = (const float*)d_in[12];
    const float* bg2       = (const float*)d_in[13];
    const float* log_decay = (const float*)d_in[14];
    float* out = (float*)d_out;

    proj_kernel<<<GRIDA, BLKA>>>(x, Wp, Wg1);
    gru_kernel<<<ROWS / RPBB, BLKB>>>(last_step, W_ih, W_hh, b_ih, b_hh,
                                      bp, Wo, bo, bg1, Wg2, bg2, log_decay, out);
}